// round 10
// baseline (speedup 1.0000x reference)
#include <cuda_runtime.h>
#include <cstdint>

#define NB   8
#define LQ   2048
#define LK   2048
#define DIN  128
#define DE   64
#define LDP  68           // padded smem leading dim (floats); 272B rows, 16B aligned
#define PANEL (64 * LDP)  // floats per 64-row smem panel

// gmem scratch: Q plain; K,V as tf32 hi/lo panels (pre-split by projections)
__device__ float g_Q [NB * LQ * DE];
__device__ float g_Kh[NB * LK * DE], g_Kl[NB * LK * DE];
__device__ float g_Vh[NB * LK * DE], g_Vl[NB * LK * DE];

// ---------------------------------------------------------------------------
// helpers
// ---------------------------------------------------------------------------
__device__ __forceinline__ uint32_t f2tf(float x) {
    uint32_t r; asm("cvt.rna.tf32.f32 %0, %1;" : "=r"(r) : "f"(x)); return r;
}
__device__ __forceinline__ void split2(float x, uint32_t& h, uint32_t& l) {
    h = f2tf(x); l = f2tf(x - __uint_as_float(h));
}
__device__ __forceinline__ uint32_t smem_u32(const void* p) {
    uint32_t a;
    asm("{ .reg .u64 t; cvta.to.shared.u64 t, %1; cvt.u32.u64 %0, t; }" : "=r"(a) : "l"(p));
    return a;
}
__device__ __forceinline__ void cpa16(uint32_t s, const void* g) {
    asm volatile("cp.async.cg.shared.global [%0], [%1], 16;" :: "r"(s), "l"(g));
}
#define CPA_COMMIT() asm volatile("cp.async.commit_group;" ::: "memory")
#define CPA_WAIT0()  asm volatile("cp.async.wait_group 0;" ::: "memory")

__device__ __forceinline__ void mma8(float* c, const uint32_t* a, uint32_t b0, uint32_t b1) {
    asm volatile(
        "mma.sync.aligned.m16n8k8.row.col.f32.tf32.tf32.f32 "
        "{%0,%1,%2,%3}, {%4,%5,%6,%7}, {%8,%9}, {%0,%1,%2,%3};"
        : "+f"(c[0]), "+f"(c[1]), "+f"(c[2]), "+f"(c[3])
        : "r"(a[0]), "r"(a[1]), "r"(a[2]), "r"(a[3]), "r"(b0), "r"(b1));
}
__device__ __forceinline__ void mma3(float* c, const uint32_t* ah, const uint32_t* al,
                                     uint32_t bh0, uint32_t bh1, uint32_t bl0, uint32_t bl1) {
    mma8(c, ah, bh0, bh1);
    mma8(c, ah, bl0, bl1);
    mma8(c, al, bh0, bh1);
}

// ---------------------------------------------------------------------------
// Projection: Out[rows,64] = X[rows,128] @ W[128,64], 3xTF32.
// SPLIT=false: plain fp32 output (Q). SPLIT=true: tf32 hi/lo panels (K, V).
// ---------------------------------------------------------------------------
template <bool SPLIT>
__global__ void __launch_bounds__(128) proj_kernel(const float* __restrict__ X,
                                                   const float* __restrict__ W,
                                                   float* __restrict__ Oh,
                                                   float* __restrict__ Ol) {
    __shared__ float Ws[DIN * LDP];
    const int tid = threadIdx.x;
    #pragma unroll 4
    for (int i = tid; i < DIN * DE; i += 128)
        Ws[(i >> 6) * LDP + (i & 63)] = W[i];
    __syncthreads();

    const int lane = tid & 31, warp = tid >> 5;
    const int g = lane >> 2, tg = lane & 3;
    const int r0 = blockIdx.x * 64 + warp * 16;
    const float* X0 = X + (size_t)(r0 + g) * DIN;
    const float* X1 = X + (size_t)(r0 + g + 8) * DIN;

    float acc[8][4];
    #pragma unroll
    for (int i = 0; i < 8; i++)
        #pragma unroll
        for (int j = 0; j < 4; j++) acc[i][j] = 0.f;

    #pragma unroll 4
    for (int kst = 0; kst < 16; kst++) {
        const int kb = kst * 8;
        uint32_t ah[4], al[4];
        split2(X0[kb + tg],     ah[0], al[0]);
        split2(X1[kb + tg],     ah[1], al[1]);
        split2(X0[kb + tg + 4], ah[2], al[2]);
        split2(X1[kb + tg + 4], ah[3], al[3]);
        #pragma unroll
        for (int nt = 0; nt < 8; nt++) {
            uint32_t bh0, bl0, bh1, bl1;
            split2(Ws[(kb + tg) * LDP + nt * 8 + g],     bh0, bl0);
            split2(Ws[(kb + tg + 4) * LDP + nt * 8 + g], bh1, bl1);
            mma3(acc[nt], ah, al, bh0, bh1, bl0, bl1);
        }
    }

    const size_t i00 = (size_t)(r0 + g) * DE;
    const size_t i08 = (size_t)(r0 + g + 8) * DE;
    #pragma unroll
    for (int nt = 0; nt < 8; nt++) {
        const int cc = nt * 8 + 2 * tg;
        if (SPLIT) {
            uint32_t h0, l0, h1, l1, h2, l2, h3, l3;
            split2(acc[nt][0], h0, l0); split2(acc[nt][1], h1, l1);
            split2(acc[nt][2], h2, l2); split2(acc[nt][3], h3, l3);
            *(float2*)&Oh[i00 + cc] = make_float2(__uint_as_float(h0), __uint_as_float(h1));
            *(float2*)&Ol[i00 + cc] = make_float2(__uint_as_float(l0), __uint_as_float(l1));
            *(float2*)&Oh[i08 + cc] = make_float2(__uint_as_float(h2), __uint_as_float(h3));
            *(float2*)&Ol[i08 + cc] = make_float2(__uint_as_float(l2), __uint_as_float(l3));
        } else {
            *(float2*)&Oh[i00 + cc] = make_float2(acc[nt][0], acc[nt][1]);
            *(float2*)&Oh[i08 + cc] = make_float2(acc[nt][2], acc[nt][3]);
        }
    }
}

// ---------------------------------------------------------------------------
// Flash attention, mma.sync tf32, pre-split operands, max-free softmax,
// double-buffered cp.async pipeline.
// grid=(16,8) = 128 blocks (one wave), 256 threads (8 warps), 128 q-rows/block,
// KV tiles of 64 rows x 2 buffers.
// smem: 2 x 4 KV panels (64xLDP) + P panel (128xLDP) = 174080 B -> 1 block/SM.
// ---------------------------------------------------------------------------
__global__ void __launch_bounds__(256, 1) attn_kernel(float* __restrict__ Out) {
    extern __shared__ float sm[];
    float* sP = sm + 8 * PANEL;   // 128 x LDP

    const int b  = blockIdx.y;
    const int q0 = blockIdx.x * 128;
    const int tid = threadIdx.x, lane = tid & 31, warp = tid >> 5;
    const int g = lane >> 2, tg = lane & 3;
    const int r0w = warp * 16;

    // ---- stage Q (128 x 64) through sP, build register tf32 hi/lo frags ----
    {
        const float* Qg = g_Q + ((size_t)b * LQ + q0) * DE;
        #pragma unroll
        for (int i = tid; i < 128 * 16; i += 256) {
            const int r = i >> 4, c4 = (i & 15) * 4;
            *(float4*)&sP[r * LDP + c4] = *(const float4*)&Qg[r * 64 + c4];
        }
    }
    __syncthreads();

    uint32_t qh[8][4], ql[8][4];
    #pragma unroll
    for (int kst = 0; kst < 8; kst++) {
        const int kb = kst * 8;
        split2(sP[(r0w + g) * LDP + kb + tg],         qh[kst][0], ql[kst][0]);
        split2(sP[(r0w + g + 8) * LDP + kb + tg],     qh[kst][1], ql[kst][1]);
        split2(sP[(r0w + g) * LDP + kb + tg + 4],     qh[kst][2], ql[kst][2]);
        split2(sP[(r0w + g + 8) * LDP + kb + tg + 4], qh[kst][3], ql[kst][3]);
    }
    __syncthreads();

    const float* Khg = g_Kh + (size_t)b * LK * DE;
    const float* Klg = g_Kl + (size_t)b * LK * DE;
    const float* Vhg = g_Vh + (size_t)b * LK * DE;
    const float* Vlg = g_Vl + (size_t)b * LK * DE;

    const uint32_t uS = smem_u32(sm);
    const int rb = tid >> 4;            // cp.async row base (rows rb + j*16)
    const int c4 = (tid & 15) * 4;

    // ---- prologue: issue tile 0 into buffer 0 ----
    {
        #pragma unroll
        for (int j = 0; j < 4; j++) {
            const int r = rb + j * 16;
            const size_t go = (size_t)r * DE + c4;
            const uint32_t so = (uint32_t)(r * LDP + c4) * 4;
            cpa16(uS + so,                     Khg + go);
            cpa16(uS + PANEL * 4 + so,         Klg + go);
            cpa16(uS + 2 * PANEL * 4 + so,     Vhg + go);
            cpa16(uS + 3 * PANEL * 4 + so,     Vlg + go);
        }
        CPA_COMMIT();
    }

    float accO[8][4];
    #pragma unroll
    for (int i = 0; i < 8; i++)
        #pragma unroll
        for (int j = 0; j < 4; j++) accO[i][j] = 0.f;
    float lp0 = 0.f, lp1 = 0.f;

    for (int t = 0; t < 32; t++) {
        CPA_WAIT0();
        __syncthreads();   // publishes buf[t&1]; also: all warps done with tile t-1

        // prefetch tile t+1 into the other buffer (overlaps with compute below)
        if (t + 1 < 32) {
            const uint32_t uB = uS + ((t + 1) & 1) * 4 * PANEL * 4;
            #pragma unroll
            for (int j = 0; j < 4; j++) {
                const int r = rb + j * 16;
                const size_t go = (size_t)((t + 1) * 64 + r) * DE + c4;
                const uint32_t so = (uint32_t)(r * LDP + c4) * 4;
                cpa16(uB + so,                 Khg + go);
                cpa16(uB + PANEL * 4 + so,     Klg + go);
                cpa16(uB + 2 * PANEL * 4 + so, Vhg + go);
                cpa16(uB + 3 * PANEL * 4 + so, Vlg + go);
            }
            CPA_COMMIT();
        }

        const float* sKh = sm + (t & 1) * 4 * PANEL;
        const float* sKl = sKh + PANEL;
        const float* sVh = sKl + PANEL;
        const float* sVl = sVh + PANEL;

        // ---- S = Q @ K^T, 3xTF32 ----
        float s[8][4];
        #pragma unroll
        for (int i = 0; i < 8; i++)
            #pragma unroll
            for (int j = 0; j < 4; j++) s[i][j] = 0.f;

        #pragma unroll
        for (int kst = 0; kst < 8; kst++) {
            const int kb = kst * 8;
            #pragma unroll
            for (int nt = 0; nt < 8; nt++) {
                const int rK = (nt * 8 + g) * LDP + kb + tg;
                const uint32_t bh0 = __float_as_uint(sKh[rK]);
                const uint32_t bh1 = __float_as_uint(sKh[rK + 4]);
                const uint32_t bl0 = __float_as_uint(sKl[rK]);
                const uint32_t bl1 = __float_as_uint(sKl[rK + 4]);
                mma3(s[nt], qh[kst], ql[kst], bh0, bh1, bl0, bl1);
            }
        }

        // ---- max-free softmax: P = exp(S) ----
        #pragma unroll
        for (int nt = 0; nt < 8; nt++) {
            const float e0 = __expf(s[nt][0]);
            const float e1 = __expf(s[nt][1]);
            const float e2 = __expf(s[nt][2]);
            const float e3 = __expf(s[nt][3]);
            lp0 += e0 + e1;
            lp1 += e2 + e3;
            *(float2*)&sP[(r0w + g) * LDP + nt * 8 + 2 * tg] =
                make_float2(__uint_as_float(f2tf(e0)), __uint_as_float(f2tf(e1)));
            *(float2*)&sP[(r0w + g + 8) * LDP + nt * 8 + 2 * tg] =
                make_float2(__uint_as_float(f2tf(e2)), __uint_as_float(f2tf(e3)));
        }
        __syncwarp();

        // ---- O += P @ V (P exact tf32; V = hi + lo) ----
        #pragma unroll
        for (int kst = 0; kst < 8; kst++) {
            const int kb = kst * 8;
            uint32_t pa[4];
            pa[0] = __float_as_uint(sP[(r0w + g) * LDP + kb + tg]);
            pa[1] = __float_as_uint(sP[(r0w + g + 8) * LDP + kb + tg]);
            pa[2] = __float_as_uint(sP[(r0w + g) * LDP + kb + tg + 4]);
            pa[3] = __float_as_uint(sP[(r0w + g + 8) * LDP + kb + tg + 4]);
            #pragma unroll
            for (int nt = 0; nt < 8; nt++) {
                const int rV0 = (kb + tg) * LDP + nt * 8 + g;
                const int rV4 = (kb + tg + 4) * LDP + nt * 8 + g;
                mma8(accO[nt], pa, __float_as_uint(sVh[rV0]), __float_as_uint(sVh[rV4]));
                mma8(accO[nt], pa, __float_as_uint(sVl[rV0]), __float_as_uint(sVl[rV4]));
            }
        }
    }

    // ---- final row sums + store ----
    lp0 += __shfl_xor_sync(0xffffffffu, lp0, 1);
    lp0 += __shfl_xor_sync(0xffffffffu, lp0, 2);
    lp1 += __shfl_xor_sync(0xffffffffu, lp1, 1);
    lp1 += __shfl_xor_sync(0xffffffffu, lp1, 2);
    const float inv0 = 1.f / lp0;
    const float inv1 = 1.f / lp1;

    float* Og = Out + ((size_t)b * LQ + q0) * DE;
    #pragma unroll
    for (int nt = 0; nt < 8; nt++) {
        *(float2*)&Og[(size_t)(r0w + g) * DE + nt * 8 + 2 * tg] =
            make_float2(accO[nt][0] * inv0, accO[nt][1] * inv0);
        *(float2*)&Og[(size_t)(r0w + g + 8) * DE + nt * 8 + 2 * tg] =
            make_float2(accO[nt][2] * inv1, accO[nt][3] * inv1);
    }
}

// ---------------------------------------------------------------------------
// Launch
// ---------------------------------------------------------------------------
extern "C" void kernel_launch(void* const* d_in, const int* in_sizes, int n_in,
                              void* d_out, int out_size) {
    const float* query = (const float*)d_in[0];
    const float* key   = (const float*)d_in[1];
    const float* W_q   = (const float*)d_in[2];
    const float* W_k   = (const float*)d_in[3];
    const float* W_v   = (const float*)d_in[4];
    float* out = (float*)d_out;

    float *q, *kh, *kl, *vh, *vl;
    cudaGetSymbolAddress((void**)&q,  g_Q);
    cudaGetSymbolAddress((void**)&kh, g_Kh);
    cudaGetSymbolAddress((void**)&kl, g_Kl);
    cudaGetSymbolAddress((void**)&vh, g_Vh);
    cudaGetSymbolAddress((void**)&vl, g_Vl);

    const int smem_attn = (8 * PANEL + 128 * LDP) * sizeof(float);  // 174080 B
    cudaFuncSetAttribute(attn_kernel, cudaFuncAttributeMaxDynamicSharedMemorySize,
                         smem_attn);

    const int pb = (NB * LQ) / 64;  // 256
    proj_kernel<false><<<pb, 128>>>(query, W_q, q,  nullptr);
    proj_kernel<true ><<<pb, 128>>>(key,   W_k, kh, kl);
    proj_kernel<true ><<<pb, 128>>>(key,   W_v, vh, vl);

    dim3 grid(LQ / 128, NB);
    attn_kernel<<<grid, 256, smem_attn>>>(out);
}

// round 12
// speedup vs baseline: 1.2684x; 1.2684x over previous
#include <cuda_runtime.h>
#include <cstdint>

#define NB   8
#define LQ   2048
#define LK   2048
#define DIN  128
#define DE   64
#define LDP  68

// gmem scratch, pre-formatted for vectorized smem fragments:
//  g_Qc/g_Kc: [b][row][128]  rows of interleaved tf32 {hi(k),hi(k+4),lo(k),lo(k+4)} quads
//  g_Vc:      [b][e][2048]   V^T, tf32, pair-permuted within each 64-kv block
__device__ float g_Qc[NB * LQ * 128];
__device__ float g_Kc[NB * LK * 128];
__device__ float g_Vc[NB * DE * LK];

// ---------------------------------------------------------------------------
// helpers
// ---------------------------------------------------------------------------
__device__ __forceinline__ uint32_t f2tf(float x) {
    uint32_t r; asm("cvt.rna.tf32.f32 %0, %1;" : "=r"(r) : "f"(x)); return r;
}
__device__ __forceinline__ void split2(float x, uint32_t& h, uint32_t& l) {
    h = f2tf(x); l = f2tf(x - __uint_as_float(h));
}
__device__ __forceinline__ uint32_t smem_u32(const void* p) {
    uint32_t a;
    asm("{ .reg .u64 t; cvta.to.shared.u64 t, %1; cvt.u32.u64 %0, t; }" : "=r"(a) : "l"(p));
    return a;
}
__device__ __forceinline__ void cpa16(uint32_t s, const void* g) {
    asm volatile("cp.async.cg.shared.global [%0], [%1], 16;" :: "r"(s), "l"(g));
}
#define CPA_COMMIT() asm volatile("cp.async.commit_group;" ::: "memory")
#define CPA_WAIT0()  asm volatile("cp.async.wait_group 0;" ::: "memory")
#define FU(x) __float_as_uint(x)

__device__ __forceinline__ void mma8(float* c, const uint32_t* a, uint32_t b0, uint32_t b1) {
    asm volatile(
        "mma.sync.aligned.m16n8k8.row.col.f32.tf32.tf32.f32 "
        "{%0,%1,%2,%3}, {%4,%5,%6,%7}, {%8,%9}, {%0,%1,%2,%3};"
        : "+f"(c[0]), "+f"(c[1]), "+f"(c[2]), "+f"(c[3])
        : "r"(a[0]), "r"(a[1]), "r"(a[2]), "r"(a[3]), "r"(b0), "r"(b1));
}
__device__ __forceinline__ void mma3(float* c, const uint32_t* ah, const uint32_t* al,
                                     uint32_t bh0, uint32_t bh1, uint32_t bl0, uint32_t bl1) {
    mma8(c, ah, bh0, bh1);
    mma8(c, ah, bl0, bl1);
    mma8(c, al, bh0, bh1);
}

// ---------------------------------------------------------------------------
// Projection: Out = X[rows,128] @ W[128,64], 3xTF32.
// MODE 0: interleaved hi/lo rows (Q, K).  MODE 1: V^T, tf32, pair-permuted.
// ---------------------------------------------------------------------------
template <int MODE>
__global__ void __launch_bounds__(128) proj_kernel(const float* __restrict__ X,
                                                   const float* __restrict__ W,
                                                   float* __restrict__ Oc) {
    __shared__ float Ws[DIN * LDP];
    const int tid = threadIdx.x;
    #pragma unroll 4
    for (int i = tid; i < DIN * DE; i += 128)
        Ws[(i >> 6) * LDP + (i & 63)] = W[i];
    __syncthreads();

    const int lane = tid & 31, warp = tid >> 5;
    const int g = lane >> 2, tg = lane & 3;
    const int r0 = blockIdx.x * 64 + warp * 16;
    const float* X0 = X + (size_t)(r0 + g) * DIN;
    const float* X1 = X + (size_t)(r0 + g + 8) * DIN;

    float acc[8][4];
    #pragma unroll
    for (int i = 0; i < 8; i++)
        #pragma unroll
        for (int j = 0; j < 4; j++) acc[i][j] = 0.f;

    #pragma unroll 4
    for (int kst = 0; kst < 16; kst++) {
        const int kb = kst * 8;
        uint32_t ah[4], al[4];
        split2(X0[kb + tg],     ah[0], al[0]);
        split2(X1[kb + tg],     ah[1], al[1]);
        split2(X0[kb + tg + 4], ah[2], al[2]);
        split2(X1[kb + tg + 4], ah[3], al[3]);
        #pragma unroll
        for (int nt = 0; nt < 8; nt++) {
            uint32_t bh0, bl0, bh1, bl1;
            split2(Ws[(kb + tg) * LDP + nt * 8 + g],     bh0, bl0);
            split2(Ws[(kb + tg + 4) * LDP + nt * 8 + g], bh1, bl1);
            mma3(acc[nt], ah, al, bh0, bh1, bl0, bl1);
        }
    }

    #pragma unroll
    for (int nt = 0; nt < 8; nt++) {
        #pragma unroll
        for (int v = 0; v < 4; v++) {
            const int R = (v < 2) ? (r0 + g) : (r0 + g + 8);
            const int e = nt * 8 + 2 * tg + (v & 1);
            if (MODE == 0) {
                uint32_t hh, ll; split2(acc[nt][v], hh, ll);
                const int pos = (e >> 3) * 16 + (e & 3) * 4 + ((e >> 2) & 1);
                Oc[(size_t)R * 128 + pos]     = __uint_as_float(hh);
                Oc[(size_t)R * 128 + pos + 2] = __uint_as_float(ll);
            } else {
                const int bb = R >> 11, kvg = R & 2047, tt = kvg >> 6, kvl = kvg & 63;
                const int pos = (kvl >> 3) * 8 + (kvl & 3) * 2 + ((kvl >> 2) & 1);
                Oc[((size_t)(bb * 64 + e)) * 2048 + tt * 64 + pos] =
                    __uint_as_float(f2tf(acc[nt][v]));
            }
        }
    }
}

// ---------------------------------------------------------------------------
// Flash attention: 8 warps = 4 q-strips (32 rows) x 2 kv-halves (32 cols).
// QK 3xTF32 via LDS.128 interleaved frags; PV 1-term (V tf32) via LDS.64.
// Max-free softmax; kv-halves merged at epilogue. One wave: grid (16,8).
// smem floats: K 2x9216 @0 | V 2x4608 @18432 | Q 18432 @27648 | P 8x1280 @46080
// ---------------------------------------------------------------------------
#define SMEM_ATTN (56320 * 4)

__global__ void __launch_bounds__(256) attn_kernel(float* __restrict__ Out) {
    extern __shared__ float smf[];
    const uint32_t sb = smem_u32(smf);
    const int tid = threadIdx.x, lane = tid & 31, warp = tid >> 5;
    const int g = lane >> 2, tg = lane & 3;
    const int qs = warp >> 1, h = warp & 1;
    const int b = blockIdx.y, q0 = blockIdx.x * 128;

    const char* Qg = (const char*)(g_Qc + ((size_t)b * LQ + q0) * 128);
    const char* Kg = (const char*)(g_Kc + (size_t)b * LK * 128);
    const char* Vg = (const char*)(g_Vc + (size_t)b * DE * LK);

    // ---- prologue: Q + K0 + V0 ----
    #pragma unroll
    for (int j = 0; j < 16; j++) { const int id = tid + j * 256, r = id >> 5, c = id & 31;
        cpa16(sb + (27648 + r * 144) * 4 + c * 16, Qg + r * 512 + c * 16); }
    #pragma unroll
    for (int j = 0; j < 8; j++) { const int id = tid + j * 256, r = id >> 5, c = id & 31;
        cpa16(sb + (r * 144) * 4 + c * 16, Kg + r * 512 + c * 16); }
    #pragma unroll
    for (int j = 0; j < 4; j++) { const int id = tid + j * 256, e = id >> 4, c = id & 15;
        cpa16(sb + (18432 + e * 72) * 4 + c * 16, Vg + (size_t)e * 8192 + c * 16); }
    CPA_COMMIT();

    float accO[2][8][4];
    #pragma unroll
    for (int i = 0; i < 2; i++)
        #pragma unroll
        for (int j = 0; j < 8; j++)
            #pragma unroll
            for (int k = 0; k < 4; k++) accO[i][j][k] = 0.f;
    float lp00 = 0.f, lp01 = 0.f, lp10 = 0.f, lp11 = 0.f;

    const int pbase = 46080 + warp * 1280;

    for (int t = 0; t < 32; t++) {
        CPA_WAIT0();
        __syncthreads();   // tile t resident; all warps done with t-1 buffers

        if (t + 1 < 32) {   // prefetch t+1 (overlaps compute below)
            const int kf = ((t + 1) & 1) * 9216;
            const int vf = 18432 + ((t + 1) & 1) * 4608;
            const char* kg = Kg + (size_t)(t + 1) * 64 * 512;
            const char* vg = Vg + (size_t)(t + 1) * 256;
            #pragma unroll
            for (int j = 0; j < 8; j++) { const int id = tid + j * 256, r = id >> 5, c = id & 31;
                cpa16(sb + (kf + r * 144) * 4 + c * 16, kg + r * 512 + c * 16); }
            #pragma unroll
            for (int j = 0; j < 4; j++) { const int id = tid + j * 256, e = id >> 4, c = id & 15;
                cpa16(sb + (vf + e * 72) * 4 + c * 16, vg + (size_t)e * 8192 + c * 16); }
            CPA_COMMIT();
        }

        const int kb0 = (t & 1) * 9216;
        const int vb0 = 18432 + (t & 1) * 4608;

        // ---- S = Q @ K^T (32q x 32kv per warp), 3xTF32 ----
        float s[2][4][4];
        #pragma unroll
        for (int i = 0; i < 2; i++)
            #pragma unroll
            for (int j = 0; j < 4; j++)
                #pragma unroll
                for (int k = 0; k < 4; k++) s[i][j][k] = 0.f;

        #pragma unroll
        for (int kst = 0; kst < 8; kst++) {
            const int qr = 27648 + (qs * 32 + g) * 144 + kst * 16 + tg * 4;
            const float4 A0 = *(const float4*)&smf[qr];
            const float4 A1 = *(const float4*)&smf[qr + 8 * 144];
            const float4 A2 = *(const float4*)&smf[qr + 16 * 144];
            const float4 A3 = *(const float4*)&smf[qr + 24 * 144];
            const uint32_t ah0[4] = {FU(A0.x), FU(A1.x), FU(A0.y), FU(A1.y)};
            const uint32_t al0[4] = {FU(A0.z), FU(A1.z), FU(A0.w), FU(A1.w)};
            const uint32_t ah1[4] = {FU(A2.x), FU(A3.x), FU(A2.y), FU(A3.y)};
            const uint32_t al1[4] = {FU(A2.z), FU(A3.z), FU(A2.w), FU(A3.w)};
            #pragma unroll
            for (int nt = 0; nt < 4; nt++) {
                const float4 B = *(const float4*)
                    &smf[kb0 + (h * 32 + nt * 8 + g) * 144 + kst * 16 + tg * 4];
                mma3(s[0][nt], ah0, al0, FU(B.x), FU(B.y), FU(B.z), FU(B.w));
                mma3(s[1][nt], ah1, al1, FU(B.x), FU(B.y), FU(B.z), FU(B.w));
            }
        }

        // ---- P = exp(S) -> per-warp smem quarter; accumulate row partials ----
        #pragma unroll
        for (int nt = 0; nt < 4; nt++) {
            {
                const float e0 = __expf(s[0][nt][0]), e1 = __expf(s[0][nt][1]);
                const float e2 = __expf(s[0][nt][2]), e3 = __expf(s[0][nt][3]);
                lp00 += e0 + e1; lp01 += e2 + e3;
                *(float2*)&smf[pbase + g * 40 + nt * 8 + 2 * tg] =
                    make_float2(__uint_as_float(f2tf(e0)), __uint_as_float(f2tf(e1)));
                *(float2*)&smf[pbase + (g + 8) * 40 + nt * 8 + 2 * tg] =
                    make_float2(__uint_as_float(f2tf(e2)), __uint_as_float(f2tf(e3)));
            }
            {
                const float e0 = __expf(s[1][nt][0]), e1 = __expf(s[1][nt][1]);
                const float e2 = __expf(s[1][nt][2]), e3 = __expf(s[1][nt][3]);
                lp10 += e0 + e1; lp11 += e2 + e3;
                *(float2*)&smf[pbase + (16 + g) * 40 + nt * 8 + 2 * tg] =
                    make_float2(__uint_as_float(f2tf(e0)), __uint_as_float(f2tf(e1)));
                *(float2*)&smf[pbase + (24 + g) * 40 + nt * 8 + 2 * tg] =
                    make_float2(__uint_as_float(f2tf(e2)), __uint_as_float(f2tf(e3)));
            }
        }
        __syncwarp();

        // ---- O += P @ V (1-term, V tf32) ----
        #pragma unroll
        for (int kst = 0; kst < 4; kst++) {
            const uint32_t a0[4] = {
                FU(smf[pbase + g * 40 + kst * 8 + tg]),
                FU(smf[pbase + (g + 8) * 40 + kst * 8 + tg]),
                FU(smf[pbase + g * 40 + kst * 8 + tg + 4]),
                FU(smf[pbase + (g + 8) * 40 + kst * 8 + tg + 4])};
            const uint32_t a1[4] = {
                FU(smf[pbase + (16 + g) * 40 + kst * 8 + tg]),
                FU(smf[pbase + (24 + g) * 40 + kst * 8 + tg]),
                FU(smf[pbase + (16 + g) * 40 + kst * 8 + tg + 4]),
                FU(smf[pbase + (24 + g) * 40 + kst * 8 + tg + 4])};
            #pragma unroll
            for (int nt = 0; nt < 8; nt++) {
                const float2 B = *(const float2*)
                    &smf[vb0 + (nt * 8 + g) * 72 + (h * 4 + kst) * 8 + tg * 2];
                mma8(accO[0][nt], a0, FU(B.x), FU(B.y));
                mma8(accO[1][nt], a1, FU(B.x), FU(B.y));
            }
        }
        __syncwarp();   // P quarter fully consumed before next tile overwrites it
    }

    // ---- epilogue: quad-reduce l, merge kv-halves via smem, store ----
    lp00 += __shfl_xor_sync(0xffffffffu, lp00, 1);
    lp00 += __shfl_xor_sync(0xffffffffu, lp00, 2);
    lp01 += __shfl_xor_sync(0xffffffffu, lp01, 1);
    lp01 += __shfl_xor_sync(0xffffffffu, lp01, 2);
    lp10 += __shfl_xor_sync(0xffffffffu, lp10, 1);
    lp10 += __shfl_xor_sync(0xffffffffu, lp10, 2);
    lp11 += __shfl_xor_sync(0xffffffffu, lp11, 1);
    lp11 += __shfl_xor_sync(0xffffffffu, lp11, 2);

    __syncthreads();
    if (h == 1) {
        const int rb = 27648 + qs * 2304;   // reuse Q region: 32 x 72 per q-strip
        #pragma unroll
        for (int rg = 0; rg < 2; rg++)
            #pragma unroll
            for (int nt = 0; nt < 8; nt++) {
                *(float2*)&smf[rb + (rg * 16 + g) * 72 + nt * 8 + 2 * tg] =
                    make_float2(accO[rg][nt][0], accO[rg][nt][1]);
                *(float2*)&smf[rb + (rg * 16 + g + 8) * 72 + nt * 8 + 2 * tg] =
                    make_float2(accO[rg][nt][2], accO[rg][nt][3]);
            }
        if (tg == 0) {
            smf[36864 + qs * 32 + g]      = lp00;
            smf[36864 + qs * 32 + g + 8]  = lp01;
            smf[36864 + qs * 32 + 16 + g] = lp10;
            smf[36864 + qs * 32 + 24 + g] = lp11;
        }
    }
    __syncthreads();
    if (h == 0) {
        const int rb = 27648 + qs * 2304;
        const int lb = 36864 + qs * 32;
        const float i00 = 1.f / (lp00 + smf[lb + g]);
        const float i01 = 1.f / (lp01 + smf[lb + g + 8]);
        const float i10 = 1.f / (lp10 + smf[lb + 16 + g]);
        const float i11 = 1.f / (lp11 + smf[lb + 24 + g]);
        float* Og = Out + ((size_t)b * LQ + q0 + qs * 32) * DE;
        #pragma unroll
        for (int rg = 0; rg < 2; rg++) {
            const float iv0 = rg ? i10 : i00;
            const float iv1 = rg ? i11 : i01;
            #pragma unroll
            for (int nt = 0; nt < 8; nt++) {
                const float2 r01 = *(const float2*)&smf[rb + (rg * 16 + g) * 72 + nt * 8 + 2 * tg];
                const float2 r23 = *(const float2*)&smf[rb + (rg * 16 + g + 8) * 72 + nt * 8 + 2 * tg];
                *(float2*)&Og[(size_t)(rg * 16 + g) * DE + nt * 8 + 2 * tg] =
                    make_float2((accO[rg][nt][0] + r01.x) * iv0,
                                (accO[rg][nt][1] + r01.y) * iv0);
                *(float2*)&Og[(size_t)(rg * 16 + g + 8) * DE + nt * 8 + 2 * tg] =
                    make_float2((accO[rg][nt][2] + r23.x) * iv1,
                                (accO[rg][nt][3] + r23.y) * iv1);
            }
        }
    }
}

// ---------------------------------------------------------------------------
// Launch
// ---------------------------------------------------------------------------
extern "C" void kernel_launch(void* const* d_in, const int* in_sizes, int n_in,
                              void* d_out, int out_size) {
    const float* query = (const float*)d_in[0];
    const float* key   = (const float*)d_in[1];
    const float* W_q   = (const float*)d_in[2];
    const float* W_k   = (const float*)d_in[3];
    const float* W_v   = (const float*)d_in[4];
    float* out = (float*)d_out;

    float *qc, *kc, *vc;
    cudaGetSymbolAddress((void**)&qc, g_Qc);
    cudaGetSymbolAddress((void**)&kc, g_Kc);
    cudaGetSymbolAddress((void**)&vc, g_Vc);

    cudaFuncSetAttribute(attn_kernel, cudaFuncAttributeMaxDynamicSharedMemorySize,
                         SMEM_ATTN);

    const int pb = (NB * LQ) / 64;  // 256
    proj_kernel<0><<<pb, 128>>>(query, W_q, qc);
    proj_kernel<0><<<pb, 128>>>(key,   W_k, kc);
    proj_kernel<1><<<pb, 128>>>(key,   W_v, vc);

    dim3 grid(LQ / 128, NB);
    attn_kernel<<<grid, 256, SMEM_ATTN>>>(out);
}

// round 13
// speedup vs baseline: 1.3162x; 1.0377x over previous
#include <cuda_runtime.h>
#include <cstdint>

#define NB   8
#define LQ   2048
#define LK   2048
#define DIN  128
#define DE   64
#define LDP  68

// gmem scratch, pre-formatted for vectorized smem fragments:
//  g_Qc/g_Kc: [b][row][128]  rows of interleaved tf32 {hi(k),hi(k+4),lo(k),lo(k+4)} quads
//  g_Vc:      [b][e][2048]   V^T, tf32, pair-permuted within each 64-kv block
__device__ float g_Qc[NB * LQ * 128];
__device__ float g_Kc[NB * LK * 128];
__device__ float g_Vc[NB * DE * LK];

// ---------------------------------------------------------------------------
// helpers
// ---------------------------------------------------------------------------
__device__ __forceinline__ uint32_t f2tf(float x) {
    uint32_t r; asm("cvt.rna.tf32.f32 %0, %1;" : "=r"(r) : "f"(x)); return r;
}
__device__ __forceinline__ void split2(float x, uint32_t& h, uint32_t& l) {
    h = f2tf(x); l = f2tf(x - __uint_as_float(h));
}
__device__ __forceinline__ uint32_t smem_u32(const void* p) {
    uint32_t a;
    asm("{ .reg .u64 t; cvta.to.shared.u64 t, %1; cvt.u32.u64 %0, t; }" : "=r"(a) : "l"(p));
    return a;
}
__device__ __forceinline__ void cpa16(uint32_t s, const void* g) {
    asm volatile("cp.async.cg.shared.global [%0], [%1], 16;" :: "r"(s), "l"(g));
}
#define CPA_COMMIT()  asm volatile("cp.async.commit_group;" ::: "memory")
#define CPA_WAITG(n)  asm volatile("cp.async.wait_group %0;" :: "n"(n) : "memory")
#define FU(x) __float_as_uint(x)

__device__ __forceinline__ void mma8(float* c, const uint32_t* a, uint32_t b0, uint32_t b1) {
    asm volatile(
        "mma.sync.aligned.m16n8k8.row.col.f32.tf32.tf32.f32 "
        "{%0,%1,%2,%3}, {%4,%5,%6,%7}, {%8,%9}, {%0,%1,%2,%3};"
        : "+f"(c[0]), "+f"(c[1]), "+f"(c[2]), "+f"(c[3])
        : "r"(a[0]), "r"(a[1]), "r"(a[2]), "r"(a[3]), "r"(b0), "r"(b1));
}
__device__ __forceinline__ void mma3(float* c, const uint32_t* ah, const uint32_t* al,
                                     uint32_t bh0, uint32_t bh1, uint32_t bl0, uint32_t bl1) {
    mma8(c, ah, bh0, bh1);
    mma8(c, ah, bl0, bl1);
    mma8(c, al, bh0, bh1);
}

// interleaved writeout helpers (layouts identical to R12, verified passing)
__device__ __forceinline__ void store_qk(float* Oc, int R, int e, float v) {
    uint32_t hh, ll; split2(v, hh, ll);
    const int pos = (e >> 3) * 16 + (e & 3) * 4 + ((e >> 2) & 1);
    Oc[(size_t)R * 128 + pos]     = __uint_as_float(hh);
    Oc[(size_t)R * 128 + pos + 2] = __uint_as_float(ll);
}
__device__ __forceinline__ void store_v(float* Oc, int R, int e, float v) {
    const int bb = R >> 11, kvg = R & 2047, tt = kvg >> 6, kvl = kvg & 63;
    const int pos = (kvl >> 3) * 8 + (kvl & 3) * 2 + ((kvl >> 2) & 1);
    Oc[((size_t)(bb * 64 + e)) * 2048 + tt * 64 + pos] = __uint_as_float(f2tf(v));
}

// ---------------------------------------------------------------------------
// Q projection: interleaved hi/lo rows
// ---------------------------------------------------------------------------
__global__ void __launch_bounds__(128) proj_q(const float* __restrict__ X,
                                              const float* __restrict__ W,
                                              float* __restrict__ Oc) {
    __shared__ float Ws[DIN * LDP];
    const int tid = threadIdx.x;
    #pragma unroll 4
    for (int i = tid; i < DIN * DE; i += 128)
        Ws[(i >> 6) * LDP + (i & 63)] = W[i];
    __syncthreads();

    const int lane = tid & 31, warp = tid >> 5;
    const int g = lane >> 2, tg = lane & 3;
    const int r0 = blockIdx.x * 64 + warp * 16;
    const float* X0 = X + (size_t)(r0 + g) * DIN;
    const float* X1 = X + (size_t)(r0 + g + 8) * DIN;

    float acc[8][4];
    #pragma unroll
    for (int i = 0; i < 8; i++)
        #pragma unroll
        for (int j = 0; j < 4; j++) acc[i][j] = 0.f;

    #pragma unroll 4
    for (int kst = 0; kst < 16; kst++) {
        const int kb = kst * 8;
        uint32_t ah[4], al[4];
        split2(X0[kb + tg],     ah[0], al[0]);
        split2(X1[kb + tg],     ah[1], al[1]);
        split2(X0[kb + tg + 4], ah[2], al[2]);
        split2(X1[kb + tg + 4], ah[3], al[3]);
        #pragma unroll
        for (int nt = 0; nt < 8; nt++) {
            uint32_t bh0, bl0, bh1, bl1;
            split2(Ws[(kb + tg) * LDP + nt * 8 + g],     bh0, bl0);
            split2(Ws[(kb + tg + 4) * LDP + nt * 8 + g], bh1, bl1);
            mma3(acc[nt], ah, al, bh0, bh1, bl0, bl1);
        }
    }

    #pragma unroll
    for (int nt = 0; nt < 8; nt++)
        #pragma unroll
        for (int v = 0; v < 4; v++) {
            const int R = (v < 2) ? (r0 + g) : (r0 + g + 8);
            store_qk(Oc, R, nt * 8 + 2 * tg + (v & 1), acc[nt][v]);
        }
}

// ---------------------------------------------------------------------------
// Fused K+V projection: one pass over `key`, shared X loads/splits.
// Dynamic smem: 2 * DIN * LDP floats (Wk, Wv panels).
// ---------------------------------------------------------------------------
__global__ void __launch_bounds__(128) proj_kv(const float* __restrict__ X,
                                               const float* __restrict__ Wk,
                                               const float* __restrict__ Wv,
                                               float* __restrict__ Kc,
                                               float* __restrict__ Vc) {
    extern __shared__ float ws[];
    float* Wks = ws;
    float* Wvs = ws + DIN * LDP;
    const int tid = threadIdx.x;
    #pragma unroll 4
    for (int i = tid; i < DIN * DE; i += 128) {
        Wks[(i >> 6) * LDP + (i & 63)] = Wk[i];
        Wvs[(i >> 6) * LDP + (i & 63)] = Wv[i];
    }
    __syncthreads();

    const int lane = tid & 31, warp = tid >> 5;
    const int g = lane >> 2, tg = lane & 3;
    const int r0 = blockIdx.x * 64 + warp * 16;
    const float* X0 = X + (size_t)(r0 + g) * DIN;
    const float* X1 = X + (size_t)(r0 + g + 8) * DIN;

    float accK[8][4], accV[8][4];
    #pragma unroll
    for (int i = 0; i < 8; i++)
        #pragma unroll
        for (int j = 0; j < 4; j++) { accK[i][j] = 0.f; accV[i][j] = 0.f; }

    #pragma unroll 2
    for (int kst = 0; kst < 16; kst++) {
        const int kb = kst * 8;
        uint32_t ah[4], al[4];
        split2(X0[kb + tg],     ah[0], al[0]);
        split2(X1[kb + tg],     ah[1], al[1]);
        split2(X0[kb + tg + 4], ah[2], al[2]);
        split2(X1[kb + tg + 4], ah[3], al[3]);
        #pragma unroll
        for (int nt = 0; nt < 8; nt++) {
            uint32_t bh0, bl0, bh1, bl1;
            split2(Wks[(kb + tg) * LDP + nt * 8 + g],     bh0, bl0);
            split2(Wks[(kb + tg + 4) * LDP + nt * 8 + g], bh1, bl1);
            mma3(accK[nt], ah, al, bh0, bh1, bl0, bl1);
            split2(Wvs[(kb + tg) * LDP + nt * 8 + g],     bh0, bl0);
            split2(Wvs[(kb + tg + 4) * LDP + nt * 8 + g], bh1, bl1);
            mma3(accV[nt], ah, al, bh0, bh1, bl0, bl1);
        }
    }

    #pragma unroll
    for (int nt = 0; nt < 8; nt++)
        #pragma unroll
        for (int v = 0; v < 4; v++) {
            const int R = (v < 2) ? (r0 + g) : (r0 + g + 8);
            const int e = nt * 8 + 2 * tg + (v & 1);
            store_qk(Kc, R, e, accK[nt][v]);
            store_v (Vc, R, e, accV[nt][v]);
        }
}

// ---------------------------------------------------------------------------
// Flash attention: 128 threads, 64 q-rows, 4 warps = 2 q-strips x 2 kv-halves.
// Single-buffered K/V with split-phase cp.async pipeline; 2 blocks/SM.
// smem floats: K @0 (64x144) | V @9216 (64x72) | Q @13824 (64x144) | P @23040 (4x1280)
// ---------------------------------------------------------------------------
#define SK 0
#define SV 9216
#define SQ 13824
#define SPB 23040
#define SMEM_ATTN (28160 * 4)   // 112640 B -> 2 blocks/SM

__global__ void __launch_bounds__(128, 2) attn_kernel(float* __restrict__ Out) {
    extern __shared__ float smf[];
    const uint32_t sb = smem_u32(smf);
    const int tid = threadIdx.x, lane = tid & 31, warp = tid >> 5;
    const int g = lane >> 2, tg = lane & 3;
    const int qs = warp >> 1, h = warp & 1;
    const int b = blockIdx.y, q0 = blockIdx.x * 64;

    const char* Qg = (const char*)(g_Qc + ((size_t)b * LQ + q0) * 128);
    const char* Kg = (const char*)(g_Kc + (size_t)b * LK * 128);
    const char* Vg = (const char*)(g_Vc + (size_t)b * DE * LK);

    // ---- prologue: group1 = Q + K0, group2 = V0 ----
    #pragma unroll
    for (int j = 0; j < 16; j++) { const int id = tid + j * 128, r = id >> 5, c = id & 31;
        cpa16(sb + (SQ + r * 144) * 4 + c * 16, Qg + r * 512 + c * 16); }
    #pragma unroll
    for (int j = 0; j < 16; j++) { const int id = tid + j * 128, r = id >> 5, c = id & 31;
        cpa16(sb + (SK + r * 144) * 4 + c * 16, Kg + r * 512 + c * 16); }
    CPA_COMMIT();
    #pragma unroll
    for (int j = 0; j < 8; j++) { const int id = tid + j * 128, e = id >> 4, c = id & 15;
        cpa16(sb + (SV + e * 72) * 4 + c * 16, Vg + (size_t)e * 8192 + c * 16); }
    CPA_COMMIT();

    float accO[2][8][4];
    #pragma unroll
    for (int i = 0; i < 2; i++)
        #pragma unroll
        for (int j = 0; j < 8; j++)
            #pragma unroll
            for (int k = 0; k < 4; k++) accO[i][j][k] = 0.f;
    float lp00 = 0.f, lp01 = 0.f, lp10 = 0.f, lp11 = 0.f;

    const int pbase = SPB + warp * 1280;

    for (int t = 0; t < 32; t++) {
        CPA_WAITG(1);          // K(t) (FIFO-older group) arrived; V(t) may trail
        __syncthreads();

        // ---- S = Q @ K^T (32q x 32kv per warp), 3xTF32 ----
        float s[2][4][4];
        #pragma unroll
        for (int i = 0; i < 2; i++)
            #pragma unroll
            for (int j = 0; j < 4; j++)
                #pragma unroll
                for (int k = 0; k < 4; k++) s[i][j][k] = 0.f;

        #pragma unroll
        for (int kst = 0; kst < 8; kst++) {
            const int qr = SQ + (qs * 32 + g) * 144 + kst * 16 + tg * 4;
            const float4 A0 = *(const float4*)&smf[qr];
            const float4 A1 = *(const float4*)&smf[qr + 8 * 144];
            const float4 A2 = *(const float4*)&smf[qr + 16 * 144];
            const float4 A3 = *(const float4*)&smf[qr + 24 * 144];
            const uint32_t ah0[4] = {FU(A0.x), FU(A1.x), FU(A0.y), FU(A1.y)};
            const uint32_t al0[4] = {FU(A0.z), FU(A1.z), FU(A0.w), FU(A1.w)};
            const uint32_t ah1[4] = {FU(A2.x), FU(A3.x), FU(A2.y), FU(A3.y)};
            const uint32_t al1[4] = {FU(A2.z), FU(A3.z), FU(A2.w), FU(A3.w)};
            #pragma unroll
            for (int nt = 0; nt < 4; nt++) {
                const float4 B = *(const float4*)
                    &smf[SK + (h * 32 + nt * 8 + g) * 144 + kst * 16 + tg * 4];
                mma3(s[0][nt], ah0, al0, FU(B.x), FU(B.y), FU(B.z), FU(B.w));
                mma3(s[1][nt], ah1, al1, FU(B.x), FU(B.y), FU(B.z), FU(B.w));
            }
        }

        __syncthreads();       // K(t) fully consumed by all warps
        if (t + 1 < 32) {      // K(t+1) load overlaps exp + PV below
            const char* kg = Kg + (size_t)(t + 1) * 64 * 512;
            #pragma unroll
            for (int j = 0; j < 16; j++) { const int id = tid + j * 128, r = id >> 5, c = id & 31;
                cpa16(sb + (SK + r * 144) * 4 + c * 16, kg + r * 512 + c * 16); }
            CPA_COMMIT();
        }

        // ---- P = exp(S) -> per-warp smem quarter ----
        #pragma unroll
        for (int nt = 0; nt < 4; nt++) {
            {
                const float e0 = __expf(s[0][nt][0]), e1 = __expf(s[0][nt][1]);
                const float e2 = __expf(s[0][nt][2]), e3 = __expf(s[0][nt][3]);
                lp00 += e0 + e1; lp01 += e2 + e3;
                *(float2*)&smf[pbase + g * 40 + nt * 8 + 2 * tg] =
                    make_float2(__uint_as_float(f2tf(e0)), __uint_as_float(f2tf(e1)));
                *(float2*)&smf[pbase + (g + 8) * 40 + nt * 8 + 2 * tg] =
                    make_float2(__uint_as_float(f2tf(e2)), __uint_as_float(f2tf(e3)));
            }
            {
                const float e0 = __expf(s[1][nt][0]), e1 = __expf(s[1][nt][1]);
                const float e2 = __expf(s[1][nt][2]), e3 = __expf(s[1][nt][3]);
                lp10 += e0 + e1; lp11 += e2 + e3;
                *(float2*)&smf[pbase + (16 + g) * 40 + nt * 8 + 2 * tg] =
                    make_float2(__uint_as_float(f2tf(e0)), __uint_as_float(f2tf(e1)));
                *(float2*)&smf[pbase + (24 + g) * 40 + nt * 8 + 2 * tg] =
                    make_float2(__uint_as_float(f2tf(e2)), __uint_as_float(f2tf(e3)));
            }
        }
        __syncwarp();

        // V(t) must be fully arrived before PV reads it
        if (t + 1 < 32) { CPA_WAITG(1); } else { CPA_WAITG(0); }
        __syncthreads();

        // ---- O += P @ V (1-term, V tf32) ----
        #pragma unroll
        for (int kst = 0; kst < 4; kst++) {
            const uint32_t a0[4] = {
                FU(smf[pbase + g * 40 + kst * 8 + tg]),
                FU(smf[pbase + (g + 8) * 40 + kst * 8 + tg]),
                FU(smf[pbase + g * 40 + kst * 8 + tg + 4]),
                FU(smf[pbase + (g + 8) * 40 + kst * 8 + tg + 4])};
            const uint32_t a1[4] = {
                FU(smf[pbase + (16 + g) * 40 + kst * 8 + tg]),
                FU(smf[pbase + (24 + g) * 40 + kst * 8 + tg]),
                FU(smf[pbase + (16 + g) * 40 + kst * 8 + tg + 4]),
                FU(smf[pbase + (24 + g) * 40 + kst * 8 + tg + 4])};
            #pragma unroll
            for (int nt = 0; nt < 8; nt++) {
                const float2 B = *(const float2*)
                    &smf[SV + (nt * 8 + g) * 72 + (h * 4 + kst) * 8 + tg * 2];
                mma8(accO[0][nt], a0, FU(B.x), FU(B.y));
                mma8(accO[1][nt], a1, FU(B.x), FU(B.y));
            }
        }
        __syncwarp();          // P quarter consumed before next tile overwrites

        __syncthreads();       // V(t) fully consumed by all warps
        if (t + 1 < 32) {      // V(t+1) load overlaps next tile's QK
            const char* vg = Vg + (size_t)(t + 1) * 256;
            #pragma unroll
            for (int j = 0; j < 8; j++) { const int id = tid + j * 128, e = id >> 4, c = id & 15;
                cpa16(sb + (SV + e * 72) * 4 + c * 16, vg + (size_t)e * 8192 + c * 16); }
            CPA_COMMIT();
        }
    }

    // ---- epilogue: quad-reduce l, merge kv-halves via smem (reuse Q region) ----
    lp00 += __shfl_xor_sync(0xffffffffu, lp00, 1);
    lp00 += __shfl_xor_sync(0xffffffffu, lp00, 2);
    lp01 += __shfl_xor_sync(0xffffffffu, lp01, 1);
    lp01 += __shfl_xor_sync(0xffffffffu, lp01, 2);
    lp10 += __shfl_xor_sync(0xffffffffu, lp10, 1);
    lp10 += __shfl_xor_sync(0xffffffffu, lp10, 2);
    lp11 += __shfl_xor_sync(0xffffffffu, lp11, 1);
    lp11 += __shfl_xor_sync(0xffffffffu, lp11, 2);

    const int rb = SQ + qs * 2304;        // 32 x 72 per q-strip
    const int lb = SQ + 4608 + qs * 32;   // 64 l-sums
    __syncthreads();
    if (h == 1) {
        #pragma unroll
        for (int rg = 0; rg < 2; rg++)
            #pragma unroll
            for (int nt = 0; nt < 8; nt++) {
                *(float2*)&smf[rb + (rg * 16 + g) * 72 + nt * 8 + 2 * tg] =
                    make_float2(accO[rg][nt][0], accO[rg][nt][1]);
                *(float2*)&smf[rb + (rg * 16 + g + 8) * 72 + nt * 8 + 2 * tg] =
                    make_float2(accO[rg][nt][2], accO[rg][nt][3]);
            }
        if (tg == 0) {
            smf[lb + g]      = lp00;
            smf[lb + g + 8]  = lp01;
            smf[lb + 16 + g] = lp10;
            smf[lb + 24 + g] = lp11;
        }
    }
    __syncthreads();
    if (h == 0) {
        const float i00 = 1.f / (lp00 + smf[lb + g]);
        const float i01 = 1.f / (lp01 + smf[lb + g + 8]);
        const float i10 = 1.f / (lp10 + smf[lb + 16 + g]);
        const float i11 = 1.f / (lp11 + smf[lb + 24 + g]);
        float* Og = Out + ((size_t)b * LQ + q0 + qs * 32) * DE;
        #pragma unroll
        for (int rg = 0; rg < 2; rg++) {
            const float iv0 = rg ? i10 : i00;
            const float iv1 = rg ? i11 : i01;
            #pragma unroll
            for (int nt = 0; nt < 8; nt++) {
                const float2 r01 = *(const float2*)&smf[rb + (rg * 16 + g) * 72 + nt * 8 + 2 * tg];
                const float2 r23 = *(const float2*)&smf[rb + (rg * 16 + g + 8) * 72 + nt * 8 + 2 * tg];
                *(float2*)&Og[(size_t)(rg * 16 + g) * DE + nt * 8 + 2 * tg] =
                    make_float2((accO[rg][nt][0] + r01.x) * iv0,
                                (accO[rg][nt][1] + r01.y) * iv0);
                *(float2*)&Og[(size_t)(rg * 16 + g + 8) * DE + nt * 8 + 2 * tg] =
                    make_float2((accO[rg][nt][2] + r23.x) * iv1,
                                (accO[rg][nt][3] + r23.y) * iv1);
            }
        }
    }
}

// ---------------------------------------------------------------------------
// Launch
// ---------------------------------------------------------------------------
extern "C" void kernel_launch(void* const* d_in, const int* in_sizes, int n_in,
                              void* d_out, int out_size) {
    const float* query = (const float*)d_in[0];
    const float* key   = (const float*)d_in[1];
    const float* W_q   = (const float*)d_in[2];
    const float* W_k   = (const float*)d_in[3];
    const float* W_v   = (const float*)d_in[4];
    float* out = (float*)d_out;

    float *qc, *kc, *vc;
    cudaGetSymbolAddress((void**)&qc, g_Qc);
    cudaGetSymbolAddress((void**)&kc, g_Kc);
    cudaGetSymbolAddress((void**)&vc, g_Vc);

    cudaFuncSetAttribute(attn_kernel, cudaFuncAttributeMaxDynamicSharedMemorySize,
                         SMEM_ATTN);
    const int smem_kv = 2 * DIN * LDP * sizeof(float);  // 69632 B
    cudaFuncSetAttribute(proj_kv, cudaFuncAttributeMaxDynamicSharedMemorySize,
                         smem_kv);

    const int pb = (NB * LQ) / 64;  // 256
    proj_q <<<pb, 128>>>(query, W_q, qc);
    proj_kv<<<pb, 128, smem_kv>>>(key, W_k, W_v, kc, vc);

    dim3 grid(LQ / 64, NB);
    attn_kernel<<<grid, 128, SMEM_ATTN>>>(out);
}

// round 14
// speedup vs baseline: 1.3337x; 1.0133x over previous
#include <cuda_runtime.h>
#include <cstdint>

#define NB   8
#define LQ   2048
#define LK   2048
#define DIN  128
#define DE   64
#define LDP  68

// gmem scratch, pre-formatted (identical layouts to R12/R13, verified):
//  g_Qc/g_Kc: [b][row][128]  rows of interleaved tf32 {hi(k),hi(k+4),lo(k),lo(k+4)} quads
//  g_Vc:      [b][e][2048]   V^T, tf32, pair-permuted within each 64-kv block
__device__ float g_Qc[NB * LQ * 128];
__device__ float g_Kc[NB * LK * 128];
__device__ float g_Vc[NB * DE * LK];

// ---------------------------------------------------------------------------
// helpers
// ---------------------------------------------------------------------------
__device__ __forceinline__ uint32_t f2tf(float x) {
    uint32_t r; asm("cvt.rna.tf32.f32 %0, %1;" : "=r"(r) : "f"(x)); return r;
}
__device__ __forceinline__ void split2(float x, uint32_t& h, uint32_t& l) {
    h = f2tf(x); l = f2tf(x - __uint_as_float(h));
}
__device__ __forceinline__ uint32_t smem_u32(const void* p) {
    uint32_t a;
    asm("{ .reg .u64 t; cvta.to.shared.u64 t, %1; cvt.u32.u64 %0, t; }" : "=r"(a) : "l"(p));
    return a;
}
__device__ __forceinline__ void cpa16(uint32_t s, const void* g) {
    asm volatile("cp.async.cg.shared.global [%0], [%1], 16;" :: "r"(s), "l"(g));
}
#define CPA_COMMIT()  asm volatile("cp.async.commit_group;" ::: "memory")
#define CPA_WAITG(n)  asm volatile("cp.async.wait_group %0;" :: "n"(n) : "memory")
#define FU(x) __float_as_uint(x)

__device__ __forceinline__ void mma8(float* c, const uint32_t* a, uint32_t b0, uint32_t b1) {
    asm volatile(
        "mma.sync.aligned.m16n8k8.row.col.f32.tf32.tf32.f32 "
        "{%0,%1,%2,%3}, {%4,%5,%6,%7}, {%8,%9}, {%0,%1,%2,%3};"
        : "+f"(c[0]), "+f"(c[1]), "+f"(c[2]), "+f"(c[3])
        : "r"(a[0]), "r"(a[1]), "r"(a[2]), "r"(a[3]), "r"(b0), "r"(b1));
}
__device__ __forceinline__ void mma3(float* c, const uint32_t* ah, const uint32_t* al,
                                     uint32_t bh0, uint32_t bh1, uint32_t bl0, uint32_t bl1) {
    mma8(c, ah, bh0, bh1);
    mma8(c, ah, bl0, bl1);
    mma8(c, al, bh0, bh1);
}

// interleaved writeout helpers (layouts identical to R12/R13, verified passing)
__device__ __forceinline__ void store_qk(float* Oc, int R, int e, float v) {
    uint32_t hh, ll; split2(v, hh, ll);
    const int pos = (e >> 3) * 16 + (e & 3) * 4 + ((e >> 2) & 1);
    Oc[(size_t)R * 128 + pos]     = __uint_as_float(hh);
    Oc[(size_t)R * 128 + pos + 2] = __uint_as_float(ll);
}
__device__ __forceinline__ void store_v(float* Oc, int R, int e, float v) {
    const int bb = R >> 11, kvg = R & 2047, tt = kvg >> 6, kvl = kvg & 63;
    const int pos = (kvl >> 3) * 8 + (kvl & 3) * 2 + ((kvl >> 2) & 1);
    Oc[((size_t)(bb * 64 + e)) * 2048 + tt * 64 + pos] = __uint_as_float(f2tf(v));
}

// ---------------------------------------------------------------------------
// Q projection: X staged in smem (vectorized), interleaved hi/lo output rows.
// Dynamic smem: W panel 128x68 + X tile 64x132.
// ---------------------------------------------------------------------------
#define PQ_WS 0
#define PQ_XS (DIN * LDP)          // 8704
#define PQ_SMEM ((DIN * LDP + 64 * 132) * 4)

__global__ void __launch_bounds__(128) proj_q(const float* __restrict__ X,
                                              const float* __restrict__ W,
                                              float* __restrict__ Oc) {
    extern __shared__ float ps[];
    float* Ws = ps + PQ_WS;
    float* Xs = ps + PQ_XS;
    const int tid = threadIdx.x;
    #pragma unroll 4
    for (int i = tid; i < DIN * DE; i += 128)
        Ws[(i >> 6) * LDP + (i & 63)] = W[i];
    {
        const float* Xg = X + (size_t)blockIdx.x * 64 * DIN;
        #pragma unroll
        for (int j = 0; j < 16; j++) {
            const int id = tid + j * 128, r = id >> 5, c = (id & 31) * 4;
            *(float4*)&Xs[r * 132 + c] = *(const float4*)&Xg[r * DIN + c];
        }
    }
    __syncthreads();

    const int lane = tid & 31, warp = tid >> 5;
    const int g = lane >> 2, tg = lane & 3;
    const int r0 = blockIdx.x * 64 + warp * 16;
    const float* X0 = Xs + (warp * 16 + g) * 132;
    const float* X1 = X0 + 8 * 132;

    float acc[8][4];
    #pragma unroll
    for (int i = 0; i < 8; i++)
        #pragma unroll
        for (int j = 0; j < 4; j++) acc[i][j] = 0.f;

    #pragma unroll 4
    for (int kst = 0; kst < 16; kst++) {
        const int kb = kst * 8;
        uint32_t ah[4], al[4];
        split2(X0[kb + tg],     ah[0], al[0]);
        split2(X1[kb + tg],     ah[1], al[1]);
        split2(X0[kb + tg + 4], ah[2], al[2]);
        split2(X1[kb + tg + 4], ah[3], al[3]);
        #pragma unroll
        for (int nt = 0; nt < 8; nt++) {
            uint32_t bh0, bl0, bh1, bl1;
            split2(Ws[(kb + tg) * LDP + nt * 8 + g],     bh0, bl0);
            split2(Ws[(kb + tg + 4) * LDP + nt * 8 + g], bh1, bl1);
            mma3(acc[nt], ah, al, bh0, bh1, bl0, bl1);
        }
    }

    #pragma unroll
    for (int nt = 0; nt < 8; nt++)
        #pragma unroll
        for (int v = 0; v < 4; v++) {
            const int R = (v < 2) ? (r0 + g) : (r0 + g + 8);
            store_qk(Oc, R, nt * 8 + 2 * tg + (v & 1), acc[nt][v]);
        }
}

// ---------------------------------------------------------------------------
// Fused K+V projection: X staged in smem, shared splits, two W panels.
// Dynamic smem: 2 W panels + X tile.
// ---------------------------------------------------------------------------
#define KV_WK 0
#define KV_WV (DIN * LDP)
#define KV_XS (2 * DIN * LDP)
#define KV_SMEM ((2 * DIN * LDP + 64 * 132) * 4)

__global__ void __launch_bounds__(128) proj_kv(const float* __restrict__ X,
                                               const float* __restrict__ Wk,
                                               const float* __restrict__ Wv,
                                               float* __restrict__ Kc,
                                               float* __restrict__ Vc) {
    extern __shared__ float ps[];
    float* Wks = ps + KV_WK;
    float* Wvs = ps + KV_WV;
    float* Xs  = ps + KV_XS;
    const int tid = threadIdx.x;
    #pragma unroll 4
    for (int i = tid; i < DIN * DE; i += 128) {
        Wks[(i >> 6) * LDP + (i & 63)] = Wk[i];
        Wvs[(i >> 6) * LDP + (i & 63)] = Wv[i];
    }
    {
        const float* Xg = X + (size_t)blockIdx.x * 64 * DIN;
        #pragma unroll
        for (int j = 0; j < 16; j++) {
            const int id = tid + j * 128, r = id >> 5, c = (id & 31) * 4;
            *(float4*)&Xs[r * 132 + c] = *(const float4*)&Xg[r * DIN + c];
        }
    }
    __syncthreads();

    const int lane = tid & 31, warp = tid >> 5;
    const int g = lane >> 2, tg = lane & 3;
    const int r0 = blockIdx.x * 64 + warp * 16;
    const float* X0 = Xs + (warp * 16 + g) * 132;
    const float* X1 = X0 + 8 * 132;

    float accK[8][4], accV[8][4];
    #pragma unroll
    for (int i = 0; i < 8; i++)
        #pragma unroll
        for (int j = 0; j < 4; j++) { accK[i][j] = 0.f; accV[i][j] = 0.f; }

    #pragma unroll 2
    for (int kst = 0; kst < 16; kst++) {
        const int kb = kst * 8;
        uint32_t ah[4], al[4];
        split2(X0[kb + tg],     ah[0], al[0]);
        split2(X1[kb + tg],     ah[1], al[1]);
        split2(X0[kb + tg + 4], ah[2], al[2]);
        split2(X1[kb + tg + 4], ah[3], al[3]);
        #pragma unroll
        for (int nt = 0; nt < 8; nt++) {
            uint32_t bh0, bl0, bh1, bl1;
            split2(Wks[(kb + tg) * LDP + nt * 8 + g],     bh0, bl0);
            split2(Wks[(kb + tg + 4) * LDP + nt * 8 + g], bh1, bl1);
            mma3(accK[nt], ah, al, bh0, bh1, bl0, bl1);
            split2(Wvs[(kb + tg) * LDP + nt * 8 + g],     bh0, bl0);
            split2(Wvs[(kb + tg + 4) * LDP + nt * 8 + g], bh1, bl1);
            mma3(accV[nt], ah, al, bh0, bh1, bl0, bl1);
        }
    }

    #pragma unroll
    for (int nt = 0; nt < 8; nt++)
        #pragma unroll
        for (int v = 0; v < 4; v++) {
            const int R = (v < 2) ? (r0 + g) : (r0 + g + 8);
            const int e = nt * 8 + 2 * tg + (v & 1);
            store_qk(Kc, R, e, accK[nt][v]);
            store_v (Vc, R, e, accV[nt][v]);
        }
}

// ---------------------------------------------------------------------------
// Flash attention: 128 threads, 32 q-rows/block, warp = 16q x 32kv
// (qs = warp>>1 selects 16-row strip, h = warp&1 selects kv-half).
// Q register-resident (loaded once, pre-interleaved), K double-buffered,
// V single-buffered split-phase. Grid (64,8) = 512 blocks, 2 blocks/SM.
// smem floats: K 2x9216 @0 | V 4608 @18432 | P 4x640 @23040  -> 102400 B
// ---------------------------------------------------------------------------
#define SK  0
#define SV  18432
#define SPB 23040
#define SMEM_ATTN (25600 * 4)

__global__ void __launch_bounds__(128, 2) attn_kernel(float* __restrict__ Out) {
    extern __shared__ float smf[];
    const uint32_t sb = smem_u32(smf);
    const int tid = threadIdx.x, lane = tid & 31, warp = tid >> 5;
    const int g = lane >> 2, tg = lane & 3;
    const int qs = warp >> 1, h = warp & 1;
    const int b = blockIdx.y, q0 = blockIdx.x * 32;

    const float* Qg = g_Qc + ((size_t)b * LQ + q0) * 128;
    const char*  Kg = (const char*)(g_Kc + (size_t)b * LK * 128);
    const char*  Vg = (const char*)(g_Vc + (size_t)b * DE * LK);

    // ---- Q fragments -> registers (16 LDG.128, once) ----
    uint32_t qh[8][4], ql[8][4];
    {
        const float* Q0 = Qg + (qs * 16 + g) * 128;
        const float* Q1 = Q0 + 8 * 128;
        #pragma unroll
        for (int kst = 0; kst < 8; kst++) {
            const float4 A = *(const float4*)&Q0[kst * 16 + tg * 4];
            const float4 B = *(const float4*)&Q1[kst * 16 + tg * 4];
            qh[kst][0] = FU(A.x); qh[kst][1] = FU(B.x);
            qh[kst][2] = FU(A.y); qh[kst][3] = FU(B.y);
            ql[kst][0] = FU(A.z); ql[kst][1] = FU(B.z);
            ql[kst][2] = FU(A.w); ql[kst][3] = FU(B.w);
        }
    }

    // ---- prologue: K0 (group), V0 (group) ----
    #pragma unroll
    for (int j = 0; j < 16; j++) { const int id = tid + j * 128, r = id >> 5, c = id & 31;
        cpa16(sb + (SK + r * 144) * 4 + c * 16, Kg + r * 512 + c * 16); }
    CPA_COMMIT();
    #pragma unroll
    for (int j = 0; j < 8; j++) { const int id = tid + j * 128, e = id >> 4, c = id & 15;
        cpa16(sb + (SV + e * 72) * 4 + c * 16, Vg + (size_t)e * 8192 + c * 16); }
    CPA_COMMIT();

    float accO[8][4];
    #pragma unroll
    for (int i = 0; i < 8; i++)
        #pragma unroll
        for (int j = 0; j < 4; j++) accO[i][j] = 0.f;
    float lp0 = 0.f, lp1 = 0.f;

    const int pbase = SPB + warp * 640;   // 16 x 40 per warp

    for (int t = 0; t < 32; t++) {
        CPA_WAITG(1);          // K(t) arrived (older group); V(t) may trail
        __syncthreads();

        if (t + 1 < 32) {      // K(t+1) into other buffer; a full tile to hide it
            const char* kg = Kg + (size_t)(t + 1) * 64 * 512;
            const int kf = SK + ((t + 1) & 1) * 9216;
            #pragma unroll
            for (int j = 0; j < 16; j++) { const int id = tid + j * 128, r = id >> 5, c = id & 31;
                cpa16(sb + (kf + r * 144) * 4 + c * 16, kg + r * 512 + c * 16); }
            CPA_COMMIT();
        }

        const int kb0 = SK + (t & 1) * 9216;

        // ---- S = Q @ K^T (16q x 32kv), 3xTF32, A in registers ----
        float s[4][4];
        #pragma unroll
        for (int j = 0; j < 4; j++)
            #pragma unroll
            for (int k = 0; k < 4; k++) s[j][k] = 0.f;

        #pragma unroll
        for (int kst = 0; kst < 8; kst++) {
            #pragma unroll
            for (int nt = 0; nt < 4; nt++) {
                const float4 B = *(const float4*)
                    &smf[kb0 + (h * 32 + nt * 8 + g) * 144 + kst * 16 + tg * 4];
                mma3(s[nt], qh[kst], ql[kst], FU(B.x), FU(B.y), FU(B.z), FU(B.w));
            }
        }

        // ---- P = exp(S) -> per-warp smem quarter ----
        #pragma unroll
        for (int nt = 0; nt < 4; nt++) {
            const float e0 = __expf(s[nt][0]), e1 = __expf(s[nt][1]);
            const float e2 = __expf(s[nt][2]), e3 = __expf(s[nt][3]);
            lp0 += e0 + e1; lp1 += e2 + e3;
            *(float2*)&smf[pbase + g * 40 + nt * 8 + 2 * tg] =
                make_float2(__uint_as_float(f2tf(e0)), __uint_as_float(f2tf(e1)));
            *(float2*)&smf[pbase + (g + 8) * 40 + nt * 8 + 2 * tg] =
                make_float2(__uint_as_float(f2tf(e2)), __uint_as_float(f2tf(e3)));
        }
        __syncwarp();

        // V(t) must be fully arrived (allow K(t+1) in flight)
        if (t + 1 < 32) { CPA_WAITG(1); } else { CPA_WAITG(0); }
        __syncthreads();

        // ---- O += P @ V (1-term, V tf32) ----
        #pragma unroll
        for (int kst = 0; kst < 4; kst++) {
            const uint32_t a[4] = {
                FU(smf[pbase + g * 40 + kst * 8 + tg]),
                FU(smf[pbase + (g + 8) * 40 + kst * 8 + tg]),
                FU(smf[pbase + g * 40 + kst * 8 + tg + 4]),
                FU(smf[pbase + (g + 8) * 40 + kst * 8 + tg + 4])};
            #pragma unroll
            for (int nt = 0; nt < 8; nt++) {
                const float2 B = *(const float2*)
                    &smf[SV + (nt * 8 + g) * 72 + (h * 4 + kst) * 8 + tg * 2];
                mma8(accO[nt], a, FU(B.x), FU(B.y));
            }
        }

        __syncthreads();       // V(t) + P consumed by all warps
        if (t + 1 < 32) {      // V(t+1) overlaps next tile's QK
            const char* vg = Vg + (size_t)(t + 1) * 256;
            #pragma unroll
            for (int j = 0; j < 8; j++) { const int id = tid + j * 128, e = id >> 4, c = id & 15;
                cpa16(sb + (SV + e * 72) * 4 + c * 16, vg + (size_t)e * 8192 + c * 16); }
            CPA_COMMIT();
        }
    }

    // ---- epilogue: quad-reduce l, merge kv-halves via smem (reuse K region) ----
    lp0 += __shfl_xor_sync(0xffffffffu, lp0, 1);
    lp0 += __shfl_xor_sync(0xffffffffu, lp0, 2);
    lp1 += __shfl_xor_sync(0xffffffffu, lp1, 1);
    lp1 += __shfl_xor_sync(0xffffffffu, lp1, 2);

    const int mb = qs * 1152;        // 16 x 72 per strip
    const int lb = 2304 + qs * 32;
    __syncthreads();
    if (h == 1) {
        #pragma unroll
        for (int nt = 0; nt < 8; nt++) {
            *(float2*)&smf[mb + g * 72 + nt * 8 + 2 * tg] =
                make_float2(accO[nt][0], accO[nt][1]);
            *(float2*)&smf[mb + (g + 8) * 72 + nt * 8 + 2 * tg] =
                make_float2(accO[nt][2], accO[nt][3]);
        }
        if (tg == 0) {
            smf[lb + g]     = lp0;
            smf[lb + g + 8] = lp1;
        }
    }
    __syncthreads();
    if (h == 0) {
        const float i0 = 1.f / (lp0 + smf[lb + g]);
        const float i1 = 1.f / (lp1 + smf[lb + g + 8]);
        float* Og = Out + ((size_t)b * LQ + q0 + qs * 16) * DE;
        #pragma unroll
        for (int nt = 0; nt < 8; nt++) {
            const float2 r01 = *(const float2*)&smf[mb + g * 72 + nt * 8 + 2 * tg];
            const float2 r23 = *(const float2*)&smf[mb + (g + 8) * 72 + nt * 8 + 2 * tg];
            *(float2*)&Og[(size_t)g * DE + nt * 8 + 2 * tg] =
                make_float2((accO[nt][0] + r01.x) * i0, (accO[nt][1] + r01.y) * i0);
            *(float2*)&Og[(size_t)(g + 8) * DE + nt * 8 + 2 * tg] =
                make_float2((accO[nt][2] + r23.x) * i1, (accO[nt][3] + r23.y) * i1);
        }
    }
}

// ---------------------------------------------------------------------------
// Launch
// ---------------------------------------------------------------------------
extern "C" void kernel_launch(void* const* d_in, const int* in_sizes, int n_in,
                              void* d_out, int out_size) {
    const float* query = (const float*)d_in[0];
    const float* key   = (const float*)d_in[1];
    const float* W_q   = (const float*)d_in[2];
    const float* W_k   = (const float*)d_in[3];
    const float* W_v   = (const float*)d_in[4];
    float* out = (float*)d_out;

    float *qc, *kc, *vc;
    cudaGetSymbolAddress((void**)&qc, g_Qc);
    cudaGetSymbolAddress((void**)&kc, g_Kc);
    cudaGetSymbolAddress((void**)&vc, g_Vc);

    cudaFuncSetAttribute(attn_kernel, cudaFuncAttributeMaxDynamicSharedMemorySize,
                         SMEM_ATTN);
    cudaFuncSetAttribute(proj_q,  cudaFuncAttributeMaxDynamicSharedMemorySize, PQ_SMEM);
    cudaFuncSetAttribute(proj_kv, cudaFuncAttributeMaxDynamicSharedMemorySize, KV_SMEM);

    const int pb = (NB * LQ) / 64;  // 256
    proj_q <<<pb, 128, PQ_SMEM>>>(query, W_q, qc);
    proj_kv<<<pb, 128, KV_SMEM>>>(key, W_k, W_v, kc, vc);

    dim3 grid(LQ / 32, NB);
    attn_kernel<<<grid, 128, SMEM_ATTN>>>(out);
}